// round 5
// baseline (speedup 1.0000x reference)
#include <cuda_runtime.h>
#include <cstdint>

#define BI 128
#define BT 128
#define RR 36
#define WW 50
#define DD 256
#define ILAMB 20.0f     // 1/0.05
#define EPSV 1e-6f

#define IP 2            // imgs per block
#define JP 2            // caps per block
#define NPAIR 4         // IP*JP
#define KC 16           // K-chunk
#define NCHUNK (DD / KC)   // 16
#define MT 3            // 48 rows padded
#define NT 7            // 56 cols padded
#define NKS (KC / 8)    // 2 k-steps per chunk

#define STRIDE 20                    // KC + 4 pad -> (20g+t)%32 bijection: conflict-free
#define A_ROWS (IP * RR)             // 72 real rows staged
#define B_ROWS (JP * WW)             // 100 real rows staged
#define A_ROWS_PAD 48                // MT*16 (per image)
#define B_ROWS_PAD 56                // NT*8  (per cap)
#define A_FLOATS (IP * A_ROWS_PAD * STRIDE)   // 1920
#define B_FLOATS (JP * B_ROWS_PAD * STRIDE)   // 2240
#define BUF_FLOATS (A_FLOATS + B_FLOATS)      // 4160
#define BUF_BYTES (BUF_FLOATS * 4)            // 16640

// Sinkhorn scratch (reuses the two staging buffers after GEMM)
#define KW 51                           // K row stride: >= WW (!) and odd (bank bijection)
#define KS_STRIDE (RR * KW)             // 1836
#define KS_FLOATS (NPAIR * KS_STRIDE)   // 7344
#define AL_OFF KS_FLOATS
#define BE_OFF (KS_FLOATS + NPAIR * RR)
#define SINK_FLOATS (KS_FLOATS + NPAIR * RR + NPAIR * WW)  // 7688

#define SMEM_FLOATS (2 * BUF_FLOATS)    // 8320 > 7688
#define SMEM_BYTES (SMEM_FLOATS * 4)    // 33280

__device__ float g_nimgs[BI * RR * DD];
__device__ float g_ncaps[BT * WW * DD];

__device__ __forceinline__ unsigned f2tf32(float x) {
    unsigned r;
    asm("cvt.rna.tf32.f32 %0, %1;" : "=r"(r) : "f"(x));
    return r;
}

__device__ __forceinline__ void cp16(uint32_t dst, const float* src) {
    asm volatile("cp.async.cg.shared.global [%0], [%1], 16;\n"
                 :: "r"(dst), "l"(src));
}

// ---------------------------------------------------------------------------
// Kernel 1: L2-normalize every row (imgs then caps), round to tf32, store.
// ---------------------------------------------------------------------------
__global__ void norm_kernel(const float* __restrict__ imgs,
                            const float* __restrict__ caps) {
    int row  = blockIdx.x * 8 + (threadIdx.x >> 5);
    int lane = threadIdx.x & 31;
    const int n_img_rows = BI * RR;
    const int n_rows = n_img_rows + BT * WW;
    if (row >= n_rows) return;

    const float* src;
    float* dst;
    if (row < n_img_rows) {
        src = imgs + (size_t)row * DD;
        dst = g_nimgs + (size_t)row * DD;
    } else {
        int r2 = row - n_img_rows;
        src = caps + (size_t)r2 * DD;
        dst = g_ncaps + (size_t)r2 * DD;
    }
    const float4* s4 = reinterpret_cast<const float4*>(src);
    float4 v0 = s4[lane];
    float4 v1 = s4[lane + 32];
    float ss = v0.x * v0.x + v0.y * v0.y + v0.z * v0.z + v0.w * v0.w
             + v1.x * v1.x + v1.y * v1.y + v1.z * v1.z + v1.w * v1.w;
#pragma unroll
    for (int o = 16; o > 0; o >>= 1) ss += __shfl_xor_sync(0xffffffffu, ss, o);
    float inv = 1.0f / fmaxf(sqrtf(ss), 1e-8f);

    float4 o0, o1;
    o0.x = __uint_as_float(f2tf32(v0.x * inv));
    o0.y = __uint_as_float(f2tf32(v0.y * inv));
    o0.z = __uint_as_float(f2tf32(v0.z * inv));
    o0.w = __uint_as_float(f2tf32(v0.w * inv));
    o1.x = __uint_as_float(f2tf32(v1.x * inv));
    o1.y = __uint_as_float(f2tf32(v1.y * inv));
    o1.z = __uint_as_float(f2tf32(v1.z * inv));
    o1.w = __uint_as_float(f2tf32(v1.w * inv));
    float4* d4 = reinterpret_cast<float4*>(dst);
    d4[lane] = o0;
    d4[lane + 32] = o1;
}

// ---------------------------------------------------------------------------
// m16n8k8 tf32 mma
// ---------------------------------------------------------------------------
__device__ __forceinline__ void mma_tf32(float* c, const uint4& a, const uint2& b) {
    asm volatile(
        "mma.sync.aligned.m16n8k8.row.col.f32.tf32.tf32.f32 "
        "{%0,%1,%2,%3}, {%4,%5,%6,%7}, {%8,%9}, {%0,%1,%2,%3};\n"
        : "+f"(c[0]), "+f"(c[1]), "+f"(c[2]), "+f"(c[3])
        : "r"(a.x), "r"(a.y), "r"(a.z), "r"(a.w), "r"(b.x), "r"(b.y));
}

// Stage one K-chunk (A: 72 real rows, B: 100 real rows) via cp.async into a
// linear [row][k] layout, stride 20 floats, rows padded per image/cap.
// KC=16 -> 4 x 16B per row. 128 threads.
__device__ __forceinline__ void stage_chunk(uint32_t sbase, int i0, int j0,
                                            int kc0, int tid) {
    // A: 72 rows * 4 = 288 LDGSTS
#pragma unroll
    for (int s = 0; s < 3; ++s) {
        int idx = tid + 128 * s;
        if (idx < A_ROWS * 4) {
            int row = idx >> 2, q = idx & 3;
            int im = (row >= RR) ? 1 : 0;
            int r = row - im * RR;
            const float* src = g_nimgs + ((size_t)(i0 + im) * RR + r) * DD + kc0 + q * 4;
            cp16(sbase + (im * A_ROWS_PAD + r) * (STRIDE * 4) + q * 16, src);
        }
    }
    // B: 100 rows * 4 = 400 LDGSTS
    uint32_t bbase = sbase + A_FLOATS * 4;
#pragma unroll
    for (int s = 0; s < 4; ++s) {
        int idx = tid + 128 * s;
        if (idx < B_ROWS * 4) {
            int row = idx >> 2, q = idx & 3;
            int jc = (row >= WW) ? 1 : 0;
            int w = row - jc * WW;
            const float* src = g_ncaps + ((size_t)(j0 + jc) * WW + w) * DD + kc0 + q * 4;
            cp16(bbase + (jc * B_ROWS_PAD + w) * (STRIDE * 4) + q * 16, src);
        }
    }
}

// ---------------------------------------------------------------------------
// Kernel 2: fused GEMM (tf32 mma.sync, cp.async double-buffered) + Sinkhorn.
// 128-thread CTA = IP(2) imgs x JP(2) caps; warp w owns pair (ii=w>>1, jj=w&1).
// ---------------------------------------------------------------------------
__global__ __launch_bounds__(128, 4)
void wass_kernel(const int* __restrict__ img_lens,
                 const int* __restrict__ cap_lens,
                 float* __restrict__ out) {
    extern __shared__ float smem[];
    const int i0 = blockIdx.y * IP;
    const int j0 = blockIdx.x * JP;
    const int tid = threadIdx.x;
    const int lane = tid & 31;
    const int wid = tid >> 5;
    const int gid = lane >> 2;
    const int tig = lane & 3;
    const int ii = wid >> 1;
    const int jj = wid & 1;

    uint32_t sb;
    asm("{ .reg .u64 t; cvta.to.shared.u64 t, %1; cvt.u32.u64 %0, t; }"
        : "=r"(sb) : "l"(smem));

    float C[MT][NT][4];
#pragma unroll
    for (int mt = 0; mt < MT; ++mt)
#pragma unroll
        for (int nt = 0; nt < NT; ++nt)
#pragma unroll
            for (int c = 0; c < 4; ++c) C[mt][nt][c] = 0.0f;

    // prologue: stage chunk 0 into buffer 0
    stage_chunk(sb, i0, j0, 0, tid);
    asm volatile("cp.async.commit_group;" ::: "memory");

    for (int ch = 0; ch < NCHUNK; ++ch) {
        if (ch + 1 < NCHUNK) {
            stage_chunk(sb + ((ch + 1) & 1) * BUF_BYTES, i0, j0, (ch + 1) * KC, tid);
            asm volatile("cp.async.commit_group;" ::: "memory");
            asm volatile("cp.async.wait_group 1;" ::: "memory");
        } else {
            asm volatile("cp.async.wait_group 0;" ::: "memory");
        }
        __syncthreads();

        const float* Abuf = smem + (ch & 1) * BUF_FLOATS + ii * (A_ROWS_PAD * STRIDE);
        const float* Bbuf = smem + (ch & 1) * BUF_FLOATS + A_FLOATS
                          + jj * (B_ROWS_PAD * STRIDE);
#pragma unroll
        for (int ks = 0; ks < NKS; ++ks) {
            uint4 a[MT];
#pragma unroll
            for (int mt = 0; mt < MT; ++mt) {
                const float* p = Abuf + (mt * 16 + gid) * STRIDE + ks * 8 + tig;
                a[mt].x = __float_as_uint(p[0]);
                a[mt].y = __float_as_uint(p[8 * STRIDE]);
                a[mt].z = __float_as_uint(p[4]);
                a[mt].w = __float_as_uint(p[8 * STRIDE + 4]);
            }
#pragma unroll
            for (int nt = 0; nt < NT; ++nt) {
                const float* q = Bbuf + (nt * 8 + gid) * STRIDE + ks * 8 + tig;
                uint2 b;
                b.x = __float_as_uint(q[0]);
                b.y = __float_as_uint(q[4]);
#pragma unroll
                for (int mt = 0; mt < MT; ++mt) mma_tf32(C[mt][nt], a[mt], b);
            }
        }
        __syncthreads();   // buffer (ch&1) free for restage / Sinkhorn reuse
    }

    // ---------------- Sinkhorn (warp-private per pair) ----------------
    const int i = i0 + ii;
    const int j = j0 + jj;
    const int Ri = img_lens[i];
    const int Wj = cap_lens[j];
    float* Kp = smem + wid * KS_STRIDE;        // [36][51]
    float* alp = smem + AL_OFF + wid * RR;     // [36]
    float* bet = smem + BE_OFF + wid * WW;     // [50]

    // K = exp((s-1)/lambda) masked; accumulate total sum
    float tsum = 0.0f;
#pragma unroll
    for (int mt = 0; mt < MT; ++mt)
#pragma unroll
        for (int nt = 0; nt < NT; ++nt)
#pragma unroll
            for (int c = 0; c < 4; ++c) {
                int r = mt * 16 + gid + ((c >> 1) << 3);
                int w = nt * 8 + (tig << 1) + (c & 1);
                if (r < Ri && w < Wj) {
                    float s = C[mt][nt][c];
                    float k = __expf(ILAMB * s - ILAMB);
                    Kp[r * KW + w] = k;
                    tsum += k;
                }
            }
#pragma unroll
    for (int o = 16; o > 0; o >>= 1) tsum += __shfl_xor_sync(0xffffffffu, tsum, o);
    float alpha0 = 1.0f / (tsum + EPSV);

    for (int r = lane; r < Ri; r += 32) alp[r] = alpha0;
    for (int w = lane; w < Wj; w += 32) bet[w] = 1.0f;
    const float rm = 1.0f / (float)Ri;
    const float cm = 1.0f / (float)Wj;
    __syncwarp();

#pragma unroll
    for (int it = 0; it < 3; ++it) {
        for (int r = lane; r < Ri; r += 32) {
            float dot = 0.0f;
            for (int w = 0; w < Wj; ++w) dot += Kp[r * KW + w] * bet[w];
            float a = alp[r];
            alp[r] = a * (rm / (a * dot + EPSV));
        }
        __syncwarp();
        for (int w = lane; w < Wj; w += 32) {
            float dot = 0.0f;
            for (int r = 0; r < Ri; ++r) dot += Kp[r * KW + w] * alp[r];
            float b = bet[w];
            bet[w] = b * (cm / (b * dot + EPSV));
        }
        __syncwarp();
    }

    // final: sum s * K * alpha_r * beta_w over valid entries
    float acc = 0.0f;
#pragma unroll
    for (int mt = 0; mt < MT; ++mt)
#pragma unroll
        for (int nt = 0; nt < NT; ++nt)
#pragma unroll
            for (int c = 0; c < 4; ++c) {
                int r = mt * 16 + gid + ((c >> 1) << 3);
                int w = nt * 8 + (tig << 1) + (c & 1);
                if (r < Ri && w < Wj) {
                    float s = C[mt][nt][c];
                    float k = __expf(ILAMB * s - ILAMB);
                    acc += s * k * alp[r] * bet[w];
                }
            }
#pragma unroll
    for (int o = 16; o > 0; o >>= 1) acc += __shfl_xor_sync(0xffffffffu, acc, o);
    if (lane == 0) out[i * BT + j] = acc;
}

// ---------------------------------------------------------------------------
extern "C" void kernel_launch(void* const* d_in, const int* in_sizes, int n_in,
                              void* d_out, int out_size) {
    const float* imgs = (const float*)d_in[0];
    const float* caps = (const float*)d_in[1];
    const int* img_lens = (const int*)d_in[2];
    const int* cap_lens = (const int*)d_in[3];
    float* out = (float*)d_out;

    cudaFuncSetAttribute(wass_kernel,
                         cudaFuncAttributeMaxDynamicSharedMemorySize, SMEM_BYTES);

    int n_rows = BI * RR + BT * WW;
    int nblk = (n_rows + 7) / 8;
    norm_kernel<<<nblk, 256>>>(imgs, caps);

    dim3 grid(BT / JP, BI / IP);  // (64, 64)
    wass_kernel<<<grid, 128, SMEM_BYTES>>>(img_lens, cap_lens, out);
}